// round 10
// baseline (speedup 1.0000x reference)
#include <cuda_runtime.h>
#include <cuda_bf16.h>

#define BATCH    16
#define TDIM     1024
#define DDIM     1024
#define RADIUS   15
#define NBLOCKS  512
#define ROW_TOTAL (64 * BATCH * 5)
#define TAU0     2.2f

typedef unsigned long long ull;

__device__ int g_counts[BATCH * DDIM];
__device__ int g_done;

__device__ __forceinline__ unsigned sortable(float f) {
    unsigned u = __float_as_uint(f);
    return u ^ (((unsigned)((int)u >> 31)) | 0x80000000u);
}
__device__ __forceinline__ float comp4(float4 v, int j) {
    return (j == 0) ? v.x : (j == 1) ? v.y : (j == 2) ? v.z : v.w;
}
__device__ __forceinline__ ull max64(ull a, ull b) { return a > b ? a : b; }

// key = (sortable(value) << 10) | (1023 - idx): value-major, lowest-index-wins.
__device__ __forceinline__ void insert5(ull key, ull& k0, ull& k1, ull& k2, ull& k3, ull& k4) {
    if (key > k4) {
        k4 = key;
        ull t;
        if (k4 > k3) { t = k3; k3 = k4; k4 = t; }
        if (k3 > k2) { t = k2; k2 = k3; k3 = t; }
        if (k2 > k1) { t = k1; k1 = k2; k2 = t; }
        if (k1 > k0) { t = k0; k0 = k1; k1 = t; }
    }
}

// 8 lanes per row (128 elems each). Branchless bitmask pass -> bit-driven
// extraction -> 8-lane shfl merge. Certified by per-row candidate count >= 5
// (then v5 >= TAU0 and candidates contain the exact top-5); cold exact serial
// fallback otherwise. Last-16 ticket blocks run the fused conv epilogue with
// the monotone poll-sum barrier (no gpu-scope fences: CCTL.IVALL flushes L1).
__global__ void __launch_bounds__(256) fused_kernel(const float* __restrict__ in,
                                                    float* __restrict__ out) {
    const unsigned FULL = 0xFFFFFFFFu;
    int lane = threadIdx.x & 31;
    int warpG = (blockIdx.x * 256 + threadIdx.x) >> 5;  // [0, 4096)
    int row = warpG * 4 + (lane >> 3);                  // [0, 16384)
    int seg = lane & 7;                                 // [0, 8)
    int g = (row & (TDIM - 1)) >> 6;

    const float* base = in + (size_t)row * DDIM + seg * 128;
    const float4* p = (const float4*)base;

    // ---- Pass 1: branchless candidate bitmask (128 bits / lane) ----
    unsigned m[4] = {0u, 0u, 0u, 0u};
#pragma unroll
    for (int w = 0; w < 4; w++) {
        float4 q[8];
#pragma unroll
        for (int j = 0; j < 8; j++) q[j] = p[w * 8 + j];
#pragma unroll
        for (int j = 0; j < 8; j++) {
#pragma unroll
            for (int e = 0; e < 4; e++) {
                if (comp4(q[j], e) >= TAU0) m[w] |= 1u << (j * 4 + e);
            }
        }
    }
    int cnt = __popc(m[0]) + __popc(m[1]) + __popc(m[2]) + __popc(m[3]);

    // ---- Row candidate total over the 8-lane group ----
    int total = cnt;
    total += __shfl_xor_sync(FULL, total, 1);
    total += __shfl_xor_sync(FULL, total, 2);
    total += __shfl_xor_sync(FULL, total, 4);
    bool fb = (total < 5);   // cold: certificate failed for this row

    // ---- Extraction: walk set bits only; per-lane sorted top-5 keys ----
    ull k0 = 0, k1 = 0, k2 = 0, k3 = 0, k4 = 0;
    if (!fb) {
#pragma unroll
        for (int w = 0; w < 4; w++) {
            unsigned mm = m[w];
            while (mm) {
                int b = __ffs(mm) - 1;
                mm &= mm - 1;
                int e = w * 32 + b;
                float f = base[e];                      // L1-hot reload
                int idx = seg * 128 + e;
                ull key = ((ull)sortable(f) << 10) | (unsigned)(1023 - idx);
                insert5(key, k0, k1, k2, k3, k4);
            }
        }
    }

    // ---- Merge: 5 rounds of 8-lane max; unique keys, winner atomics + pops ----
    // (uniform across the warp: fb lanes hold zero keys and never win)
#pragma unroll
    for (int r = 0; r < 5; r++) {
        ull h = k0;
        h = max64(h, __shfl_xor_sync(FULL, h, 1));
        h = max64(h, __shfl_xor_sync(FULL, h, 2));
        h = max64(h, __shfl_xor_sync(FULL, h, 4));
        if (!fb && h != 0 && k0 == h) {
            int idx = 1023 - (int)(h & 1023u);
            atomicAdd(&g_counts[g * DDIM + idx], 1);
            k0 = k1; k1 = k2; k2 = k3; k3 = k4; k4 = 0;
        }
    }

    // ---- Cold exact fallback: lane 0 of a failed row scans the whole row ----
    if (fb && seg == 0) {
        const float4* rp = (const float4*)(in + (size_t)row * DDIM);
        ull s0 = 0, s1 = 0, s2 = 0, s3 = 0, s4 = 0;
        for (int i = 0; i < 256; i++) {
            float4 q = rp[i];
#pragma unroll
            for (int e = 0; e < 4; e++) {
                ull key = ((ull)sortable(comp4(q, e)) << 10) |
                          (unsigned)(1023 - (i * 4 + e));
                insert5(key, s0, s1, s2, s3, s4);
            }
        }
        atomicAdd(&g_counts[g * DDIM + (1023 - (int)(s0 & 1023u))], 1);
        atomicAdd(&g_counts[g * DDIM + (1023 - (int)(s1 & 1023u))], 1);
        atomicAdd(&g_counts[g * DDIM + (1023 - (int)(s2 & 1023u))], 1);
        atomicAdd(&g_counts[g * DDIM + (1023 - (int)(s3 & 1023u))], 1);
        atomicAdd(&g_counts[g * DDIM + (1023 - (int)(s4 & 1023u))], 1);
    }

    // ================= epilogue: last 16 ticket-takers run the conv =================
    __shared__ int s_ticket;
    __syncthreads();
    if (threadIdx.x == 0) s_ticket = atomicAdd(&g_done, 1);
    __syncthreads();
    int ticket = s_ticket;
    if (ticket < NBLOCKS - BATCH) return;

    if (ticket == NBLOCKS - 1 && threadIdx.x == 0) g_done = 0;  // all increments applied
    int crow = ticket - (NBLOCKS - BATCH);
    int tid = threadIdx.x;

    __shared__ float srow[DDIM + 2 * RADIUS];
    __shared__ float w[2 * RADIUS + 1];
    __shared__ int wsum[8];
    __shared__ int s_sum;

    if (tid < 2 * RADIUS + 1) {
        int k = tid - RADIUS;
        w[tid] = 0.19947114020071635f * expf(-0.125f * (float)(k * k));
    }
    if (tid < RADIUS) { srow[tid] = 0.0f; srow[DDIM + RADIUS + tid] = 0.0f; }

    // Poll-sum barrier: monotone counts + total match == consistent final snapshot.
    const int4* rowp = (const int4*)(g_counts + crow * DDIM);
    while (true) {
        int4 c4 = __ldcg(rowp + tid);
        srow[RADIUS + tid * 4 + 0] = (float)c4.x;
        srow[RADIUS + tid * 4 + 1] = (float)c4.y;
        srow[RADIUS + tid * 4 + 2] = (float)c4.z;
        srow[RADIUS + tid * 4 + 3] = (float)c4.w;
        int part = c4.x + c4.y + c4.z + c4.w;
#pragma unroll
        for (int off = 16; off; off >>= 1) part += __shfl_xor_sync(FULL, part, off);
        if ((tid & 31) == 0) wsum[tid >> 5] = part;
        __syncthreads();
        if (tid == 0) {
            int t = 0;
#pragma unroll
            for (int i = 0; i < 8; i++) t += wsum[i];
            s_sum = t;
        }
        __syncthreads();
        if (s_sum == ROW_TOTAL) break;
        __nanosleep(100);
    }

    ((int4*)(g_counts + crow * DDIM))[tid] = make_int4(0, 0, 0, 0);

    float4 acc;
#pragma unroll
    for (int i = 0; i < 4; i++) {
        int d = tid * 4 + i;
        float a = 0.0f;
#pragma unroll
        for (int k = 0; k < 2 * RADIUS + 1; k++) a += srow[d + k] * w[k];
        ((float*)&acc)[i] = a;
    }
    ((float4*)(out + crow * DDIM))[tid] = acc;
}

extern "C" void kernel_launch(void* const* d_in, const int* in_sizes, int n_in,
                              void* d_out, int out_size) {
    const float* in = (const float*)d_in[0];
    float* out = (float*)d_out;
    fused_kernel<<<NBLOCKS, 256>>>(in, out);
}

// round 11
// speedup vs baseline: 4.3939x; 4.3939x over previous
#include <cuda_runtime.h>
#include <cuda_bf16.h>

#define BATCH    16
#define TDIM     1024
#define DDIM     1024
#define RADIUS   15
#define NBLOCKS  2048
#define ROW_TOTAL (64 * BATCH * 5)
#define TAU0     2.2f

typedef unsigned long long ull;

__device__ int g_counts[BATCH * DDIM];
__device__ int g_done;

__device__ __forceinline__ unsigned sortable(float f) {
    unsigned u = __float_as_uint(f);
    return u ^ (((unsigned)((int)u >> 31)) | 0x80000000u);
}
__device__ __forceinline__ float unsortable(unsigned s) {
    unsigned u = (s & 0x80000000u) ? (s ^ 0x80000000u) : ~s;
    return __uint_as_float(u);
}
__device__ __forceinline__ float comp4(float4 v, int j) {
    return (j == 0) ? v.x : (j == 1) ? v.y : (j == 2) ? v.z : v.w;
}

// One warp per row, 32 elems/lane (MLP=8 float4 loads — the R7-proven layout).
// Branchless 32-bit candidate mask replaces both the knockout REDUX chain and
// all value-test rescans; extraction & rescans are ffs/bit-driven with scalar
// L1-hot reloads. Certificate: warp candidate count >= 5 => v5 >= TAU0 =>
// candidate set contains the exact top-5. Cold exact fallback otherwise.
// Fused conv epilogue w/ monotone poll-sum barrier (no gpu-scope fences).
__global__ void __launch_bounds__(256, 6) fused_kernel(const float* __restrict__ in,
                                                       float* __restrict__ out) {
    const unsigned FULL = 0xFFFFFFFFu;
    int warp = (blockIdx.x * 256 + threadIdx.x) >> 5;   // row id [0, 16384)
    int lane = threadIdx.x & 31;
    int g = (warp & (TDIM - 1)) >> 6;

    const float* rowbase = in + (size_t)warp * DDIM;
    const float4* p = (const float4*)rowbase + lane;

    // ---- Pass 1: 8 independent LDG.128, branchless candidate mask ----
    // element index for bit b (=4c+j): 4*lane + 128*(b>>2) + (b&3)
    unsigned m = 0;
    {
        float4 q[8];
#pragma unroll
        for (int c = 0; c < 8; c++) q[c] = p[c * 32];
#pragma unroll
        for (int c = 0; c < 8; c++) {
#pragma unroll
            for (int j = 0; j < 4; j++) {
                if (comp4(q[c], j) >= TAU0) m |= 1u << (c * 4 + j);
            }
        }
    }

    float tauf = TAU0;
    int cnt = __popc(m);
    int cntW = __reduce_add_sync(FULL, cnt);

    if (__builtin_expect(cntW < 5, 0)) {
        // ---- Cold exact fallback: knockout tau from L1 reloads, re-mask ----
        float4 q[8];
#pragma unroll
        for (int c = 0; c < 8; c++) q[c] = p[c * 32];
        float lmax = __int_as_float(0xFF800000);
#pragma unroll
        for (int c = 0; c < 8; c++)
            lmax = fmaxf(lmax, fmaxf(fmaxf(q[c].x, q[c].y), fmaxf(q[c].z, q[c].w)));
        unsigned s = sortable(lmax);
        unsigned tau_s = 0;
#pragma unroll
        for (int r = 0; r < 5; r++) {
            unsigned best = __reduce_max_sync(FULL, s);
            tau_s = best;
            if (s == best) s = 0;   // drop ties: tau only shrinks (still a valid bound)
        }
        tauf = unsortable(tau_s);
        m = 0;
#pragma unroll
        for (int c = 0; c < 8; c++) {
#pragma unroll
            for (int j = 0; j < 4; j++) {
                if (comp4(q[c], j) >= tauf) m |= 1u << (c * 4 + j);
            }
        }
        cnt = __popc(m);
    }

    // ---- Phase C: per-lane best key via bit walk (E[bits] = 0.44/lane) ----
    // key = (sortable(value) << 10) | (1023 - idx): value-major, lowest-index-wins.
    ull ck = 0;
    {
        unsigned mm = m;
        while (mm) {
            int b = __ffs(mm) - 1;
            mm &= mm - 1;
            int idx = 4 * lane + ((b >> 2) << 7) + (b & 3);
            float f = rowbase[idx];                     // L1-hot scalar reload
            ull key = ((ull)sortable(f) << 10) | (unsigned)(1023 - idx);
            if (key > ck) ck = key;
        }
    }

    // ---- Phase D: exact top-5 extraction (value, lowest-index tie-break) ----
    int myidx = 0;
#pragma unroll
    for (int r = 0; r < 5; r++) {
        unsigned hi = (unsigned)(ck >> 10);
        unsigned bestv = __reduce_max_sync(FULL, hi);
        unsigned myinv = (unsigned)(ck & 1023u);
        unsigned inv_c = (hi == bestv) ? myinv : 0u;
        unsigned besti = __reduce_max_sync(FULL, inv_c);
        if (lane == r) myidx = 1023 - (int)besti;
        if (hi == bestv && myinv == besti) {            // unique winner lane
            cnt--;
            ull ub = ck;
            ull nk = 0;
            if (cnt > 0) {                               // rescan own bits for next-best
                unsigned mm = m;
                while (mm) {
                    int b = __ffs(mm) - 1;
                    mm &= mm - 1;
                    int idx = 4 * lane + ((b >> 2) << 7) + (b & 3);
                    float f = rowbase[idx];
                    ull key = ((ull)sortable(f) << 10) | (unsigned)(1023 - idx);
                    if (key < ub && key > nk) nk = key;
                }
            }
            ck = nk;
        }
    }

    if (lane < 5) atomicAdd(&g_counts[g * DDIM + myidx], 1);

    // ================= epilogue: last 16 ticket-takers run the conv =================
    __shared__ int s_ticket;
    __syncthreads();
    if (threadIdx.x == 0) s_ticket = atomicAdd(&g_done, 1);
    __syncthreads();
    int ticket = s_ticket;
    if (ticket < NBLOCKS - BATCH) return;

    if (ticket == NBLOCKS - 1 && threadIdx.x == 0) g_done = 0;  // all increments applied
    int crow = ticket - (NBLOCKS - BATCH);
    int tid = threadIdx.x;

    __shared__ float srow[DDIM + 2 * RADIUS];
    __shared__ float w[2 * RADIUS + 1];
    __shared__ int wsum[8];
    __shared__ int s_sum;

    if (tid < 2 * RADIUS + 1) {
        int k = tid - RADIUS;
        w[tid] = 0.19947114020071635f * expf(-0.125f * (float)(k * k));
    }
    if (tid < RADIUS) { srow[tid] = 0.0f; srow[DDIM + RADIUS + tid] = 0.0f; }

    // Poll-sum barrier: monotone counts + total match == consistent final snapshot.
    const int4* rowp = (const int4*)(g_counts + crow * DDIM);
    while (true) {
        int4 c4 = __ldcg(rowp + tid);                   // L2-coherent, bypass L1
        srow[RADIUS + tid * 4 + 0] = (float)c4.x;
        srow[RADIUS + tid * 4 + 1] = (float)c4.y;
        srow[RADIUS + tid * 4 + 2] = (float)c4.z;
        srow[RADIUS + tid * 4 + 3] = (float)c4.w;
        int part = c4.x + c4.y + c4.z + c4.w;
#pragma unroll
        for (int off = 16; off; off >>= 1) part += __shfl_xor_sync(FULL, part, off);
        if ((tid & 31) == 0) wsum[tid >> 5] = part;
        __syncthreads();
        if (tid == 0) {
            int t = 0;
#pragma unroll
            for (int i = 0; i < 8; i++) t += wsum[i];
            s_sum = t;
        }
        __syncthreads();
        if (s_sum == ROW_TOTAL) break;
        __nanosleep(100);
    }

    ((int4*)(g_counts + crow * DDIM))[tid] = make_int4(0, 0, 0, 0);

    float4 acc;
#pragma unroll
    for (int i = 0; i < 4; i++) {
        int d = tid * 4 + i;
        float a = 0.0f;
#pragma unroll
        for (int k = 0; k < 2 * RADIUS + 1; k++) a += srow[d + k] * w[k];
        ((float*)&acc)[i] = a;
    }
    ((float4*)(out + crow * DDIM))[tid] = acc;
}

extern "C" void kernel_launch(void* const* d_in, const int* in_sizes, int n_in,
                              void* d_out, int out_size) {
    const float* in = (const float*)d_in[0];
    float* out = (float*)d_out;
    fused_kernel<<<NBLOCKS, 256>>>(in, out);
}